// round 4
// baseline (speedup 1.0000x reference)
#include <cuda_runtime.h>
#include <math.h>

#define NKNOT 1024
#define NW    1020   // NUM_KNOTS - DEGREE - 1

// fp32 images of +/-pi (== np.linspace endpoints after float32 cast)
#define T_LO (-3.14159274101257324218750f)
#define T_HI ( 3.14159274101257324218750f)
// 1023/(2*pi), correctly rounded fp32
#define INV_H 162.81578063964843750f
// pi * 1023/(2*pi) = 511.5 exactly
#define S_OFF 511.5f

#define THREADS 256
#define ELEMS   2

// ---------------------------------------------------------------------------
// Compile-time replica of np.linspace(-pi, pi, 1024).astype(float32):
//   step = (stop-start)/1023 (f64);  y_i = fl32(fl64(i*step) + start);
//   endpoint pinned to fl32(stop).
// ---------------------------------------------------------------------------
struct KnotTable { float v[NKNOT]; };
constexpr KnotTable make_knots() {
    KnotTable K{};
    const double start = -3.141592653589793;
    const double stop  =  3.141592653589793;
    const double step  = (stop - start) / 1023.0;
    for (int i = 0; i < NKNOT; i++) {
        double m = (double)i * step;
        K.v[i] = (float)(m + start);
    }
    K.v[NKNOT - 1] = (float)stop;
    return K;
}
__device__ constexpr KnotTable g_knots = make_knots();

__global__ __launch_bounds__(THREADS) void bspline_act_kernel(
    const float* __restrict__ x,
    const float* __restrict__ w,
    float* __restrict__ out)
{
    __shared__ float s_knot[NKNOT];   // 4 KB
    __shared__ float s_w[NKNOT];      // 4 KB (1020 used; pad entries zeroed)

    const int tid = threadIdx.x;

    // ---- prologue: pure copy, one float4 per thread per table ----
    {
        const float4* k4 = reinterpret_cast<const float4*>(g_knots.v);
        reinterpret_cast<float4*>(s_knot)[tid] = k4[tid];            // 256*16B = 4KB exact

        if (tid < NW / 4) {                                          // 255 threads
            const float4* w4 = reinterpret_cast<const float4*>(w);
            reinterpret_cast<float4*>(s_w)[tid] = w4[tid];
        } else {                                                     // zero the 4-float pad
            reinterpret_cast<float4*>(s_w)[tid] = make_float4(0.f, 0.f, 0.f, 0.f);
        }
    }
    __syncthreads();

    // ---- main: 2 elements per thread, loads batched for MLP ----
    const int base = (blockIdx.x * THREADS + tid) * ELEMS;
    float2 xv = *reinterpret_cast<const float2*>(x + base);
    float xs[2] = {xv.x, xv.y};
    float r[2];

    int   iv[2];
    float u[2];
#pragma unroll
    for (int e = 0; e < 2; e++) {
        float s = fmaf(xs[e], INV_H, S_OFF);
        int i = (int)s;                       // trunc; negatives only from rounding fuzz -> 0
        i = min(max(i, 0), NKNOT - 2);
        iv[e] = i;
        u[e] = (xs[e] - s_knot[i]) * INV_H;   // exact subtraction of nearby floats
    }

#pragma unroll
    for (int e = 0; e < 2; e++) {
        int   i  = iv[e];
        float uu = u[e];
        int   c  = i - 3;

        // 4 parallel LDS; out-of-range weights are zero-padded or select-zeroed
        float w0 = s_w[min(max(c,     0), NKNOT - 1)];
        float w1 = s_w[min(max(c + 1, 0), NKNOT - 1)];
        float w2 = s_w[min(max(c + 2, 0), NKNOT - 1)];
        float w3 = s_w[i];                                 // i <= 1022, pad is zero
        w0 = (c     >= 0) ? w0 : 0.0f;
        w1 = (c + 1 >= 0) ? w1 : 0.0f;
        w2 = (c + 2 >= 0) ? w2 : 0.0f;
        w0 = (c     < NW) ? w0 : 0.0f;
        w1 = (c + 1 < NW) ? w1 : 0.0f;
        w2 = (c + 2 < NW) ? w2 : 0.0f;
        w3 = (i     < NW) ? w3 : 0.0f;

        const float SIXTH = 0.16666666666666666f;
        float omu = 1.0f - uu;
        float u2  = uu * uu;
        float u3  = u2 * uu;
        float N0 = omu * omu * omu * SIXTH;
        float N1 = fmaf(3.0f, u3, fmaf(-6.0f, u2, 4.0f)) * SIXTH;
        float N2 = fmaf(-3.0f, u3, fmaf(3.0f, u2, fmaf(3.0f, uu, 1.0f))) * SIXTH;
        float N3 = u3 * SIXTH;

        float acc = fmaf(N0, w0, fmaf(N1, w1, fmaf(N2, w2, N3 * w3)));
        bool in = (xs[e] >= T_LO) && (xs[e] < T_HI);
        r[e] = in ? acc : 0.0f;
    }

    *reinterpret_cast<float2*>(out + base) = make_float2(r[0], r[1]);
}

extern "C" void kernel_launch(void* const* d_in, const int* in_sizes, int n_in,
                              void* d_out, int out_size) {
    const float* x = (const float*)d_in[0];
    const float* w = (const float*)d_in[1];
    float* out = (float*)d_out;
    int n = in_sizes[0];                                  // 262144
    int blocks = n / (THREADS * ELEMS);                   // 512, exact cover
    bspline_act_kernel<<<blocks, THREADS>>>(x, w, out);
}

// round 5
// speedup vs baseline: 1.0047x; 1.0047x over previous
#include <cuda_runtime.h>
#include <math.h>

#define NKNOT 1024
#define NW    1020          // NUM_KNOTS - DEGREE - 1

// fp32 images of +/-pi (np.linspace endpoints after float32 cast)
#define T_LO (-3.14159274101257324218750f)
#define T_HI ( 3.14159274101257324218750f)

// 1023/(2*pi) split into hi+lo floats (hi = correctly-rounded fp32, lo = residual)
#define INVH_HI 162.81578063964843750f
#define INVH_LO (-8.2343605185432045e-08f)
#define S_OFF   511.5f       // pi * 1023/(2*pi), exactly representable

#define THREADS 256
#define ELEMS   2
#define TBL     1032         // 4 zero + 1020 weights + 8 zero

__global__ __launch_bounds__(THREADS) void bspline_act_kernel(
    const float* __restrict__ x,
    const float* __restrict__ w,
    float* __restrict__ out)
{
    // s_big[j+4] = w[j]; zeros at [0..3] and [1024..1031].
    // Tap k of interval i is w[i-3+k] = s_big[i+1+k], always in range, no clamps.
    __shared__ float s_big[TBL];

    const int tid = threadIdx.x;

    // ---- prologue: pure copy, one float4 per thread ----
    if (tid < NW / 4) {                                         // 255 threads
        reinterpret_cast<float4*>(s_big + 4)[tid] =
            reinterpret_cast<const float4*>(w)[tid];
    } else {                                                    // tid == 255: zero pads
        float4 z = make_float4(0.f, 0.f, 0.f, 0.f);
        reinterpret_cast<float4*>(s_big)[0]   = z;              // [0..3]
        reinterpret_cast<float4*>(s_big)[256] = z;              // [1024..1027]
        reinterpret_cast<float4*>(s_big)[257] = z;              // [1028..1031]
    }
    __syncthreads();

    // ---- main: 2 elements per thread ----
    const int base = (blockIdx.x * THREADS + tid) * ELEMS;
    float2 xv = *reinterpret_cast<const float2*>(x + base);
    float xs[2] = {xv.x, xv.y};
    float r[2];

#pragma unroll
    for (int e = 0; e < 2; e++) {
        float xx = xs[e];

        // interval index
        float s1 = fmaf(xx, INVH_HI, S_OFF);
        int i = (int)s1;
        i = min(max(i, 0), NKNOT - 2);

        // local coordinate, compensated: 511.5 - i is exact, single-rounding fma,
        // lo-term corrects INVH_HI's representation error.
        float offi = S_OFF - (float)i;
        float u = fmaf(xx, INVH_LO, fmaf(xx, INVH_HI, offi));

        // 4 weight taps, unconditional
        float w0 = s_big[i + 1];
        float w1 = s_big[i + 2];
        float w2 = s_big[i + 3];
        float w3 = s_big[i + 4];

        // uniform cubic B-spline blend
        const float SIXTH = 0.16666666666666666f;
        float omu = 1.0f - u;
        float u2  = u * u;
        float u3  = u2 * u;
        float N0 = omu * omu * omu * SIXTH;
        float N1 = fmaf(3.0f, u3, fmaf(-6.0f, u2, 4.0f)) * SIXTH;
        float N2 = fmaf(-3.0f, u3, fmaf(3.0f, u2, fmaf(3.0f, u, 1.0f))) * SIXTH;
        float N3 = u3 * SIXTH;

        float acc = fmaf(N0, w0, fmaf(N1, w1, fmaf(N2, w2, N3 * w3)));
        r[e] = (xx >= T_LO && xx < T_HI) ? acc : 0.0f;
    }

    *reinterpret_cast<float2*>(out + base) = make_float2(r[0], r[1]);
}

extern "C" void kernel_launch(void* const* d_in, const int* in_sizes, int n_in,
                              void* d_out, int out_size) {
    const float* x = (const float*)d_in[0];
    const float* w = (const float*)d_in[1];
    float* out = (float*)d_out;
    int n = in_sizes[0];                         // 262144
    int blocks = n / (THREADS * ELEMS);          // 512, exact cover
    bspline_act_kernel<<<blocks, THREADS>>>(x, w, out);
}

// round 6
// speedup vs baseline: 1.0435x; 1.0386x over previous
#include <cuda_runtime.h>
#include <math.h>

#define NKNOT 1024
#define NW    1020          // NUM_KNOTS - DEGREE - 1

// fp32 images of +/-pi (np.linspace endpoints after float32 cast)
#define T_LO (-3.14159274101257324218750f)
#define T_HI ( 3.14159274101257324218750f)

// 1023/(2*pi) split hi+lo (hi = correctly-rounded fp32, lo = residual)
#define INVH_HI 162.81578063964843750f
#define INVH_LO (-8.2343605185432045e-08f)
#define S_OFF   511.5f       // pi * 1023/(2*pi), exactly representable

#define THREADS 256
#define ELEMS   4
#define TBL     1032         // 4 zero + 1020 weights + 8 zero

__global__ __launch_bounds__(THREADS) void bspline_act_kernel(
    const float* __restrict__ x,
    const float* __restrict__ w,
    float* __restrict__ out)
{
    // s_big[j+4] = w[j]; zeros at [0..3] and [1024..1031].
    // Tap k of interval i is w[i-3+k] = s_big[i+1+k] — always in range, no clamps.
    __shared__ float s_big[TBL];

    const int tid  = threadIdx.x;
    const int base = (blockIdx.x * THREADS + tid) * ELEMS;

    // ---- prefetch x FIRST: its latency overlaps the prologue + barrier ----
    float4 xv = *reinterpret_cast<const float4*>(x + base);

    // ---- prologue: pure copy, one float4 per thread ----
    if (tid < NW / 4) {                                         // 255 threads
        reinterpret_cast<float4*>(s_big + 4)[tid] =
            reinterpret_cast<const float4*>(w)[tid];
    } else {                                                    // tid == 255: zero pads
        float4 z = make_float4(0.f, 0.f, 0.f, 0.f);
        reinterpret_cast<float4*>(s_big)[0]   = z;              // [0..3]
        reinterpret_cast<float4*>(s_big)[256] = z;              // [1024..1027]
        reinterpret_cast<float4*>(s_big)[257] = z;              // [1028..1031]
    }
    __syncthreads();

    float xs[4] = {xv.x, xv.y, xv.z, xv.w};
    float r[4];

#pragma unroll
    for (int e = 0; e < 4; e++) {
        float xx = xs[e];

        // interval index
        float s1 = fmaf(xx, INVH_HI, S_OFF);
        int i = (int)s1;
        i = min(max(i, 0), NKNOT - 2);

        // compensated local coordinate: 511.5 - i exact; lo-term fixes INVH_HI's
        // representation error. u accurate to ~1e-7 vs ideal uniform grid.
        float offi = S_OFF - (float)i;
        float u = fmaf(xx, INVH_LO, fmaf(xx, INVH_HI, offi));

        // 4 unconditional weight taps (parallel LDS)
        float w0 = s_big[i + 1];
        float w1 = s_big[i + 2];
        float w2 = s_big[i + 3];
        float w3 = s_big[i + 4];

        // uniform cubic B-spline blend
        const float SIXTH = 0.16666666666666666f;
        float omu = 1.0f - u;
        float u2  = u * u;
        float u3  = u2 * u;
        float N0 = omu * omu * omu * SIXTH;
        float N1 = fmaf(3.0f, u3, fmaf(-6.0f, u2, 4.0f)) * SIXTH;
        float N2 = fmaf(-3.0f, u3, fmaf(3.0f, u2, fmaf(3.0f, u, 1.0f))) * SIXTH;
        float N3 = u3 * SIXTH;

        float acc = fmaf(N0, w0, fmaf(N1, w1, fmaf(N2, w2, N3 * w3)));
        r[e] = (xx >= T_LO && xx < T_HI) ? acc : 0.0f;
    }

    *reinterpret_cast<float4*>(out + base) = make_float4(r[0], r[1], r[2], r[3]);
}

extern "C" void kernel_launch(void* const* d_in, const int* in_sizes, int n_in,
                              void* d_out, int out_size) {
    const float* x = (const float*)d_in[0];
    const float* w = (const float*)d_in[1];
    float* out = (float*)d_out;
    int n = in_sizes[0];                         // 262144
    int blocks = n / (THREADS * ELEMS);          // 256, exact cover
    bspline_act_kernel<<<blocks, THREADS>>>(x, w, out);
}